// round 2
// baseline (speedup 1.0000x reference)
#include <cuda_runtime.h>
#include <math.h>

// Problem constants
#define D_     512
#define TD_    1024     // 2*D
#define NSYM_  512
#define NCON_  64
#define NV_    256      // vocab == logits dim
#define B_     32
#define S_     512
#define NPOS_  (B_*S_)  // 16384
#define DEPTH_ 6
#define EPS_   1e-8f
#define CC_    0.25f
#define SCALE_ 0.04419417382415922f   // 512^-0.5

// ---------------------------------------------------------------------------
// Static device scratch (no allocations allowed)
// ---------------------------------------------------------------------------
__device__ float g_embed[NV_*TD_];      // [256,1024] concat(zr,zi) per vocab
__device__ float g_z0[NV_*TD_];         // cell(embed)
__device__ float g_cellTab[NSYM_*TD_];  // cell(sym_k)
__device__ float g_C2[NSYM_*TD_];       // cell^2(sym_k)
__device__ float g_C3[NSYM_*TD_];       // cell^3(sym_k)
__device__ float g_lookOut[NSYM_*NV_];  // decode(cell^3(sym_k))
__device__ float g_Ksym[NSYM_*D_];      // kw proj of sym
__device__ float g_Vsym[NSYM_*TD_];     // vw proj of sym
__device__ float g_Qtab[NSYM_*D_];      // qw proj of cellTab
__device__ float g_QK[NSYM_*NSYM_];     // Qtab . Ksym
__device__ float g_CS[NSYM_*NSYM_];     // cellTab . sym
__device__ float g_VS[NSYM_*NSYM_];     // Vsym . sym
__device__ float g_Z0S[NV_*NSYM_];      // z0 . sym
__device__ float g_SymCon[NSYM_*NCON_]; // sym . con
__device__ float g_sym2[NSYM_];
__device__ float g_con2[NCON_];
__device__ float g_conDist[NSYM_];      // min_j dist(sym_k, con_j)
__device__ float g_outTab[NV_*NV_];     // final output row per vocab id
__device__ float g_symLv[NV_];          // per-vocab sum of sym quantize dists
__device__ float g_conLv[NV_];          // per-vocab sum of con quantize dists

// ---------------------------------------------------------------------------
// Embedding: zr = mag*cos(phase), zi = mag*sin(phase), stored concat
// ---------------------------------------------------------------------------
__global__ void embed_kernel(const float* __restrict__ mag,
                             const float* __restrict__ phase)
{
    int v = blockIdx.x;
    for (int i = threadIdx.x; i < D_; i += blockDim.x) {
        float r = mag[v*D_ + i];
        float t = phase[v*D_ + i];
        g_embed[v*TD_ + i]       = r * cosf(t);
        g_embed[v*TD_ + D_ + i]  = r * sinf(t);
    }
}

// ---------------------------------------------------------------------------
// Generic tiled fp32 GEMM: C[M,N] = A[M,K] @ B[N,K]^T (+ bias[N])
// M,N multiples of 64, K multiple of 16.
// ---------------------------------------------------------------------------
#define BM 64
#define BN 64
#define BK 16

__global__ __launch_bounds__(256)
void gemm_abt(const float* __restrict__ A, const float* __restrict__ Bw,
              const float* __restrict__ bias, float* __restrict__ C,
              int M, int N, int K)
{
    __shared__ float As[BM][BK+1];
    __shared__ float Bs[BN][BK+1];
    const int tid = threadIdx.x;
    const int tx  = tid & 15, ty = tid >> 4;
    const int m0  = blockIdx.y * BM, n0 = blockIdx.x * BN;
    const int lr  = tid >> 2, lc = (tid & 3) << 2;

    float acc[4][4];
#pragma unroll
    for (int i = 0; i < 4; i++)
#pragma unroll
        for (int j = 0; j < 4; j++) acc[i][j] = 0.f;

    for (int k0 = 0; k0 < K; k0 += BK) {
        float4 av = *(const float4*)(A  + (size_t)(m0+lr)*K + k0 + lc);
        float4 bv = *(const float4*)(Bw + (size_t)(n0+lr)*K + k0 + lc);
        As[lr][lc+0] = av.x; As[lr][lc+1] = av.y; As[lr][lc+2] = av.z; As[lr][lc+3] = av.w;
        Bs[lr][lc+0] = bv.x; Bs[lr][lc+1] = bv.y; Bs[lr][lc+2] = bv.z; Bs[lr][lc+3] = bv.w;
        __syncthreads();
#pragma unroll
        for (int k = 0; k < BK; k++) {
            float a0 = As[ty*4+0][k], a1 = As[ty*4+1][k], a2 = As[ty*4+2][k], a3 = As[ty*4+3][k];
            float b0 = Bs[tx*4+0][k], b1 = Bs[tx*4+1][k], b2 = Bs[tx*4+2][k], b3 = Bs[tx*4+3][k];
            acc[0][0] += a0*b0; acc[0][1] += a0*b1; acc[0][2] += a0*b2; acc[0][3] += a0*b3;
            acc[1][0] += a1*b0; acc[1][1] += a1*b1; acc[1][2] += a1*b2; acc[1][3] += a1*b3;
            acc[2][0] += a2*b0; acc[2][1] += a2*b1; acc[2][2] += a2*b2; acc[2][3] += a2*b3;
            acc[3][0] += a3*b0; acc[3][1] += a3*b1; acc[3][2] += a3*b2; acc[3][3] += a3*b3;
        }
        __syncthreads();
    }
#pragma unroll
    for (int i = 0; i < 4; i++) {
        int m = m0 + ty*4 + i;
#pragma unroll
        for (int j = 0; j < 4; j++) {
            int n = n0 + tx*4 + j;
            float v = acc[i][j];
            if (bias) v += bias[n];
            C[(size_t)m*N + n] = v;
        }
    }
}

// ---------------------------------------------------------------------------
// Complex recurrent cell applied row-wise to a [M, 2D] concat state:
//   lr = zr@Wr^T - zi@Wi^T ; li = zi@Wr^T + zr@Wi^T
//   m = sqrt(lr^2+li^2+eps); out = tanh(l/(1+m)), stored concat
// ---------------------------------------------------------------------------
__global__ __launch_bounds__(256)
void cell_kernel(const float* __restrict__ Zin, const float* __restrict__ Wr,
                 const float* __restrict__ Wi, float* __restrict__ Zout, int M)
{
    __shared__ float Ar[BM][BK+1];
    __shared__ float Ai[BM][BK+1];
    __shared__ float Br[BN][BK+1];
    __shared__ float Bi[BN][BK+1];
    const int tid = threadIdx.x;
    const int tx  = tid & 15, ty = tid >> 4;
    const int m0  = blockIdx.y * BM, n0 = blockIdx.x * BN;
    const int lr_ = tid >> 2, lc = (tid & 3) << 2;

    float accR[4][4], accI[4][4];
#pragma unroll
    for (int i = 0; i < 4; i++)
#pragma unroll
        for (int j = 0; j < 4; j++) { accR[i][j] = 0.f; accI[i][j] = 0.f; }

    for (int k0 = 0; k0 < D_; k0 += BK) {
        float4 ar4 = *(const float4*)(Zin + (size_t)(m0+lr_)*TD_ + k0 + lc);
        float4 ai4 = *(const float4*)(Zin + (size_t)(m0+lr_)*TD_ + D_ + k0 + lc);
        float4 wr4 = *(const float4*)(Wr  + (size_t)(n0+lr_)*D_ + k0 + lc);
        float4 wi4 = *(const float4*)(Wi  + (size_t)(n0+lr_)*D_ + k0 + lc);
        Ar[lr_][lc+0]=ar4.x; Ar[lr_][lc+1]=ar4.y; Ar[lr_][lc+2]=ar4.z; Ar[lr_][lc+3]=ar4.w;
        Ai[lr_][lc+0]=ai4.x; Ai[lr_][lc+1]=ai4.y; Ai[lr_][lc+2]=ai4.z; Ai[lr_][lc+3]=ai4.w;
        Br[lr_][lc+0]=wr4.x; Br[lr_][lc+1]=wr4.y; Br[lr_][lc+2]=wr4.z; Br[lr_][lc+3]=wr4.w;
        Bi[lr_][lc+0]=wi4.x; Bi[lr_][lc+1]=wi4.y; Bi[lr_][lc+2]=wi4.z; Bi[lr_][lc+3]=wi4.w;
        __syncthreads();
#pragma unroll
        for (int k = 0; k < BK; k++) {
            float ar[4], ai[4], br[4], bi[4];
#pragma unroll
            for (int i = 0; i < 4; i++) { ar[i] = Ar[ty*4+i][k]; ai[i] = Ai[ty*4+i][k]; }
#pragma unroll
            for (int j = 0; j < 4; j++) { br[j] = Br[tx*4+j][k]; bi[j] = Bi[tx*4+j][k]; }
#pragma unroll
            for (int i = 0; i < 4; i++)
#pragma unroll
                for (int j = 0; j < 4; j++) {
                    accR[i][j] += ar[i]*br[j] - ai[i]*bi[j];
                    accI[i][j] += ai[i]*br[j] + ar[i]*bi[j];
                }
        }
        __syncthreads();
    }
#pragma unroll
    for (int i = 0; i < 4; i++) {
        int m = m0 + ty*4 + i;
#pragma unroll
        for (int j = 0; j < 4; j++) {
            int n = n0 + tx*4 + j;
            float lr = accR[i][j], li = accI[i][j];
            float mm = sqrtf(lr*lr + li*li + EPS_);
            lr = lr / (1.f + mm);
            li = li / (1.f + mm);
            Zout[(size_t)m*TD_ + n]       = tanhf(lr);
            Zout[(size_t)m*TD_ + D_ + n]  = tanhf(li);
        }
    }
}

// ---------------------------------------------------------------------------
// Row-wise squared norms
// ---------------------------------------------------------------------------
__global__ void rownorm_kernel(const float* __restrict__ A, float* __restrict__ out, int C)
{
    __shared__ float red[256];
    int r = blockIdx.x, tid = threadIdx.x;
    float s = 0.f;
    for (int i = tid; i < C; i += 256) { float v = A[(size_t)r*C + i]; s += v*v; }
    red[tid] = s; __syncthreads();
    for (int st = 128; st > 0; st >>= 1) {
        if (tid < st) red[tid] += red[tid+st];
        __syncthreads();
    }
    if (tid == 0) out[r] = red[0];
}

// conDist[k] = min_j (|sym_k|^2 + |con_j|^2 - 2 sym_k.con_j)
__global__ void condist_kernel()
{
    int k = blockIdx.x*blockDim.x + threadIdx.x;
    if (k < NSYM_) {
        float best = 1e30f;
        float s2 = g_sym2[k];
        for (int j = 0; j < NCON_; j++) {
            float d = s2 + g_con2[j] - 2.f*g_SymCon[k*NCON_ + j];
            if (d < best) best = d;
        }
        g_conDist[k] = best;
    }
}

// ---------------------------------------------------------------------------
// Trajectory kernel: one block per vocab id. Simulates iterations 0..5 using
// precomputed tables, producing per-vocab output row + loss sums.
// ---------------------------------------------------------------------------
__global__ __launch_bounds__(256)
void trajectory_kernel()
{
    __shared__ float red[256];
    __shared__ float sdist[256];
    __shared__ int   sidx[256];
    __shared__ int   memIdx[DEPTH_];
    __shared__ float wsh[DEPTH_];
    __shared__ float sh_conf;

    const int v = blockIdx.x, tid = threadIdx.x;

    // ---- iteration 0: |z0|^2 then argmin over sym distances ----
    float part = 0.f;
    for (int i = tid; i < TD_; i += 256) { float z = g_z0[(size_t)v*TD_ + i]; part += z*z; }
    red[tid] = part; __syncthreads();
    for (int st = 128; st > 0; st >>= 1) { if (tid < st) red[tid] += red[tid+st]; __syncthreads(); }
    float z2 = red[0];
    __syncthreads();

    float bd = 1e30f; int bi = 0;
    for (int kp = tid; kp < NSYM_; kp += 256) {
        float d = z2 + g_sym2[kp] - 2.f*g_Z0S[(size_t)v*NSYM_ + kp];
        if (d < bd) { bd = d; bi = kp; }
    }
    sdist[tid] = bd; sidx[tid] = bi; __syncthreads();
    for (int st = 128; st > 0; st >>= 1) {
        if (tid < st) {
            float d2 = sdist[tid+st]; int i2 = sidx[tid+st];
            if (d2 < sdist[tid] || (d2 == sdist[tid] && i2 < sidx[tid])) { sdist[tid] = d2; sidx[tid] = i2; }
        }
        __syncthreads();
    }
    int si = sidx[0]; float sd = sdist[0];
    if (tid == 0) { memIdx[0] = si; sh_conf = 1.f/(1.f + sd); }
    float symL = sd;
    float conL = g_conDist[si];
    __syncthreads();

    // ---- iterations 1..5 ----
    for (int d = 1; d < DEPTH_; d++) {
        int k = memIdx[d-1];
        if (tid == 0) {
            float sc[DEPTH_]; float mx = -1e30f;
            float cf = sh_conf;
            for (int j = 0; j < d; j++) {
                float s = g_QK[(size_t)k*NSYM_ + memIdx[j]] * SCALE_ * cf;
                sc[j] = s; if (s > mx) mx = s;
            }
            float se = 0.f;
            for (int j = 0; j < d; j++) { sc[j] = expf(sc[j]-mx); se += sc[j]; }
            for (int j = 0; j < d; j++) wsh[j] = sc[j]/se;
        }
        __syncthreads();

        // |z|^2 with z = cellTab[k] + 0.1 * sum_j w_j Vsym[mem_j]
        part = 0.f;
        for (int i = tid; i < TD_; i += 256) {
            float z = g_cellTab[(size_t)k*TD_ + i];
            for (int j = 0; j < d; j++)
                z += 0.1f * wsh[j] * g_Vsym[(size_t)memIdx[j]*TD_ + i];
            part += z*z;
        }
        red[tid] = part; __syncthreads();
        for (int st = 128; st > 0; st >>= 1) { if (tid < st) red[tid] += red[tid+st]; __syncthreads(); }
        z2 = red[0];
        __syncthreads();

        // distances via tables, argmin
        bd = 1e30f; bi = 0;
        for (int kp = tid; kp < NSYM_; kp += 256) {
            float zdot = g_CS[(size_t)k*NSYM_ + kp];
            for (int j = 0; j < d; j++)
                zdot += 0.1f * wsh[j] * g_VS[(size_t)memIdx[j]*NSYM_ + kp];
            float dist = z2 + g_sym2[kp] - 2.f*zdot;
            if (dist < bd) { bd = dist; bi = kp; }
        }
        sdist[tid] = bd; sidx[tid] = bi; __syncthreads();
        for (int st = 128; st > 0; st >>= 1) {
            if (tid < st) {
                float d2 = sdist[tid+st]; int i2 = sidx[tid+st];
                if (d2 < sdist[tid] || (d2 == sdist[tid] && i2 < sidx[tid])) { sdist[tid] = d2; sidx[tid] = i2; }
            }
            __syncthreads();
        }
        si = sidx[0]; sd = sdist[0];
        if (tid == 0) { memIdx[d] = si; sh_conf = 1.f/(1.f + sd); }
        symL += sd;
        conL += g_conDist[si];
        __syncthreads();
    }

    int si5 = memIdx[DEPTH_-1];
    g_outTab[(size_t)v*NV_ + tid] = g_lookOut[(size_t)si5*NV_ + tid];
    if (tid == 0) { g_symLv[v] = symL; g_conLv[v] = conL; }
}

// ---------------------------------------------------------------------------
// Output scatter: out[p,:] = outTab[x[p],:]
// ---------------------------------------------------------------------------
__global__ void scatter_kernel(const int* __restrict__ x, float* __restrict__ out)
{
    int p = blockIdx.x;
    int v = __ldg(&x[p]);
    out[(size_t)p*NV_ + threadIdx.x] = g_outTab[(size_t)v*NV_ + threadIdx.x];
}

// ---------------------------------------------------------------------------
// Histogram + scalar losses (single block)
// ---------------------------------------------------------------------------
__global__ void histloss_kernel(const int* __restrict__ x, float* __restrict__ out, int writeLoss)
{
    __shared__ int   hist[NV_];
    __shared__ float red[256];
    int tid = threadIdx.x;
    hist[tid] = 0; __syncthreads();
    for (int i = tid; i < NPOS_; i += 256) atomicAdd(&hist[x[i]], 1);
    __syncthreads();

    float h = (float)hist[tid];
    float s = h * g_symLv[tid];
    float c = h * g_conLv[tid];

    red[tid] = s; __syncthreads();
    for (int st = 128; st > 0; st >>= 1) { if (tid < st) red[tid] += red[tid+st]; __syncthreads(); }
    float st_tot = red[0]; __syncthreads();

    red[tid] = c; __syncthreads();
    for (int st = 128; st > 0; st >>= 1) { if (tid < st) red[tid] += red[tid+st]; __syncthreads(); }
    float ct_tot = red[0];

    if (tid == 0 && writeLoss) {
        float norm = (1.f + CC_) / (float)((size_t)NPOS_ * TD_);
        out[(size_t)NPOS_*NV_]     = st_tot * norm;
        out[(size_t)NPOS_*NV_ + 1] = ct_tot * norm;
    }
}

// ---------------------------------------------------------------------------
// Host launcher
// ---------------------------------------------------------------------------
extern "C" void kernel_launch(void* const* d_in, const int* in_sizes, int n_in,
                              void* d_out, int out_size)
{
    const int*   x     = (const int*)d_in[0];
    const float* mag   = (const float*)d_in[1];
    const float* phase = (const float*)d_in[2];
    const float* Wr    = (const float*)d_in[3];
    const float* Wi    = (const float*)d_in[4];
    const float* qw    = (const float*)d_in[5];
    const float* qb    = (const float*)d_in[6];
    const float* kw    = (const float*)d_in[7];
    const float* kb    = (const float*)d_in[8];
    const float* vw    = (const float*)d_in[9];
    const float* vb    = (const float*)d_in[10];
    const float* dec_w = (const float*)d_in[11];
    const float* dec_b = (const float*)d_in[12];
    const float* sym   = (const float*)d_in[13];
    const float* con   = (const float*)d_in[14];
    float* out = (float*)d_out;

    // Resolve device-global scratch addresses (host-side query; not a stream op)
    float *pEmbed, *pZ0, *pCellTab, *pC2, *pC3, *pLookOut, *pKsym, *pVsym,
          *pQtab, *pQK, *pCS, *pVS, *pZ0S, *pSymCon, *pSym2, *pCon2;
    cudaGetSymbolAddress((void**)&pEmbed,   g_embed);
    cudaGetSymbolAddress((void**)&pZ0,      g_z0);
    cudaGetSymbolAddress((void**)&pCellTab, g_cellTab);
    cudaGetSymbolAddress((void**)&pC2,      g_C2);
    cudaGetSymbolAddress((void**)&pC3,      g_C3);
    cudaGetSymbolAddress((void**)&pLookOut, g_lookOut);
    cudaGetSymbolAddress((void**)&pKsym,    g_Ksym);
    cudaGetSymbolAddress((void**)&pVsym,    g_Vsym);
    cudaGetSymbolAddress((void**)&pQtab,    g_Qtab);
    cudaGetSymbolAddress((void**)&pQK,      g_QK);
    cudaGetSymbolAddress((void**)&pCS,      g_CS);
    cudaGetSymbolAddress((void**)&pVS,      g_VS);
    cudaGetSymbolAddress((void**)&pZ0S,     g_Z0S);
    cudaGetSymbolAddress((void**)&pSymCon,  g_SymCon);
    cudaGetSymbolAddress((void**)&pSym2,    g_sym2);
    cudaGetSymbolAddress((void**)&pCon2,    g_con2);

    // 1. Embedding table (256 vocab rows)
    embed_kernel<<<NV_, 256>>>(mag, phase);

    // 2. Cell applications
    cell_kernel<<<dim3(D_/BN, NV_/BM),   256>>>(pEmbed,   Wr, Wi, pZ0,      NV_);
    cell_kernel<<<dim3(D_/BN, NSYM_/BM), 256>>>(sym,      Wr, Wi, pCellTab, NSYM_);
    cell_kernel<<<dim3(D_/BN, NSYM_/BM), 256>>>(pCellTab, Wr, Wi, pC2,      NSYM_);
    cell_kernel<<<dim3(D_/BN, NSYM_/BM), 256>>>(pC2,      Wr, Wi, pC3,      NSYM_);

    // 3. Table GEMMs
    gemm_abt<<<dim3(NV_/BN,   NSYM_/BM), 256>>>(pC3,      dec_w, dec_b,  pLookOut, NSYM_, NV_,   TD_);
    gemm_abt<<<dim3(D_/BN,    NSYM_/BM), 256>>>(sym,      kw,    kb,     pKsym,    NSYM_, D_,    TD_);
    gemm_abt<<<dim3(TD_/BN,   NSYM_/BM), 256>>>(sym,      vw,    vb,     pVsym,    NSYM_, TD_,   TD_);
    gemm_abt<<<dim3(D_/BN,    NSYM_/BM), 256>>>(pCellTab, qw,    qb,     pQtab,    NSYM_, D_,    TD_);
    gemm_abt<<<dim3(NSYM_/BN, NSYM_/BM), 256>>>(pQtab,    pKsym, nullptr,pQK,      NSYM_, NSYM_, D_);
    gemm_abt<<<dim3(NSYM_/BN, NSYM_/BM), 256>>>(pCellTab, sym,   nullptr,pCS,      NSYM_, NSYM_, TD_);
    gemm_abt<<<dim3(NSYM_/BN, NSYM_/BM), 256>>>(pVsym,    sym,   nullptr,pVS,      NSYM_, NSYM_, TD_);
    gemm_abt<<<dim3(NSYM_/BN, NV_/BM),   256>>>(pZ0,      sym,   nullptr,pZ0S,     NV_,   NSYM_, TD_);
    gemm_abt<<<dim3(NCON_/BN, NSYM_/BM), 256>>>(sym,      con,   nullptr,pSymCon,  NSYM_, NCON_, TD_);

    // 4. Norms + con distances
    rownorm_kernel<<<NSYM_, 256>>>(sym, pSym2, TD_);
    rownorm_kernel<<<NCON_, 256>>>(con, pCon2, TD_);
    condist_kernel<<<2, 256>>>();

    // 5. 256 vocab trajectories (iterations 0..5, argmins, losses)
    trajectory_kernel<<<NV_, 256>>>();

    // 6. Output scatter + scalar losses
    scatter_kernel<<<NPOS_, NV_>>>(x, out);
    int writeLoss = (out_size >= NPOS_*NV_ + 2) ? 1 : 0;
    histloss_kernel<<<1, 256>>>(x, out, writeLoss);
}

// round 3
// speedup vs baseline: 2.0195x; 2.0195x over previous
#include <cuda_runtime.h>
#include <math.h>

// Problem constants
#define D_     512
#define TD_    1024     // 2*D
#define NSYM_  512
#define NCON_  64
#define NV_    256      // vocab == logits dim
#define B_     32
#define S_     512
#define NPOS_  (B_*S_)  // 16384
#define DEPTH_ 6
#define EPS_   1e-8f
#define CC_    0.25f
#define SCALE_ 0.04419417382415922f   // 512^-0.5

#define BM 64
#define BN 64
#define BK 16
#define SM_PLANE (64*(BK+1))     // 1088 floats per smem plane
#define SM_FLOATS (4*SM_PLANE)   // 4352 floats = 17408 B

// ---------------------------------------------------------------------------
// Static device scratch
// ---------------------------------------------------------------------------
__device__ float g_embed[NV_*TD_];
__device__ float g_z0[NV_*TD_];
__device__ float g_cellTab[NSYM_*TD_];
__device__ float g_C2[NSYM_*TD_];
__device__ float g_C3[NSYM_*TD_];
__device__ float g_lookP[4][NSYM_*NV_];   // split-K partials of decode(C3)
__device__ float g_Ksym[NSYM_*D_];
__device__ float g_Vsym[NSYM_*TD_];
__device__ float g_Qtab[NSYM_*D_];
__device__ float g_QK[NSYM_*NSYM_];
__device__ float g_CS[NSYM_*NSYM_];
__device__ float g_VS[NSYM_*NSYM_];
__device__ float g_Z0S[NV_*NSYM_];
__device__ float g_SymCon[NSYM_*NCON_];
__device__ float g_sym2[NSYM_];
__device__ float g_con2[NCON_];
__device__ float g_conDist[NSYM_];
__device__ int   g_fin[NV_];              // final symbol index per vocab
__device__ float g_symLv[NV_];
__device__ float g_conLv[NV_];

// ---------------------------------------------------------------------------
// Device GEMM tile: C[by*64.., bx*64..] = A[M,K](rows) @ B[N,K]^T (+bias)
// over k in [kBeg,kEnd). K = row stride of both A and B.
// ---------------------------------------------------------------------------
__device__ __forceinline__ void dev_gemm_tile(
    const float* __restrict__ A, const float* __restrict__ Bw,
    const float* __restrict__ bias, float* __restrict__ C,
    int N, int K, int kBeg, int kEnd, int bx, int by, float* sm)
{
    float (*As)[BK+1] = (float (*)[BK+1])sm;
    float (*Bs)[BK+1] = (float (*)[BK+1])(sm + SM_PLANE);
    const int tid = threadIdx.x;
    const int tx  = tid & 15, ty = tid >> 4;
    const int m0  = by * BM, n0 = bx * BN;
    const int lr  = tid >> 2, lc = (tid & 3) << 2;

    float acc[4][4];
#pragma unroll
    for (int i = 0; i < 4; i++)
#pragma unroll
        for (int j = 0; j < 4; j++) acc[i][j] = 0.f;

    for (int k0 = kBeg; k0 < kEnd; k0 += BK) {
        float4 av = *(const float4*)(A  + (size_t)(m0+lr)*K + k0 + lc);
        float4 bv = *(const float4*)(Bw + (size_t)(n0+lr)*K + k0 + lc);
        As[lr][lc+0] = av.x; As[lr][lc+1] = av.y; As[lr][lc+2] = av.z; As[lr][lc+3] = av.w;
        Bs[lr][lc+0] = bv.x; Bs[lr][lc+1] = bv.y; Bs[lr][lc+2] = bv.z; Bs[lr][lc+3] = bv.w;
        __syncthreads();
#pragma unroll
        for (int k = 0; k < BK; k++) {
            float a0 = As[ty*4+0][k], a1 = As[ty*4+1][k], a2 = As[ty*4+2][k], a3 = As[ty*4+3][k];
            float b0 = Bs[tx*4+0][k], b1 = Bs[tx*4+1][k], b2 = Bs[tx*4+2][k], b3 = Bs[tx*4+3][k];
            acc[0][0] += a0*b0; acc[0][1] += a0*b1; acc[0][2] += a0*b2; acc[0][3] += a0*b3;
            acc[1][0] += a1*b0; acc[1][1] += a1*b1; acc[1][2] += a1*b2; acc[1][3] += a1*b3;
            acc[2][0] += a2*b0; acc[2][1] += a2*b1; acc[2][2] += a2*b2; acc[2][3] += a2*b3;
            acc[3][0] += a3*b0; acc[3][1] += a3*b1; acc[3][2] += a3*b2; acc[3][3] += a3*b3;
        }
        __syncthreads();
    }
#pragma unroll
    for (int i = 0; i < 4; i++) {
        int m = m0 + ty*4 + i;
#pragma unroll
        for (int j = 0; j < 4; j++) {
            int n = n0 + tx*4 + j;
            float v = acc[i][j];
            if (bias) v += bias[n];
            C[(size_t)m*N + n] = v;
        }
    }
}

// ---------------------------------------------------------------------------
// Device cell tile: complex recurrent cell on concat [M,2D] state
// ---------------------------------------------------------------------------
__device__ __forceinline__ void dev_cell_tile(
    const float* __restrict__ Zin, const float* __restrict__ Wr,
    const float* __restrict__ Wi, float* __restrict__ Zout,
    int bx, int by, float* sm)
{
    float (*Ar)[BK+1] = (float (*)[BK+1])sm;
    float (*Ai)[BK+1] = (float (*)[BK+1])(sm + SM_PLANE);
    float (*Br)[BK+1] = (float (*)[BK+1])(sm + 2*SM_PLANE);
    float (*Bi)[BK+1] = (float (*)[BK+1])(sm + 3*SM_PLANE);
    const int tid = threadIdx.x;
    const int tx  = tid & 15, ty = tid >> 4;
    const int m0  = by * BM, n0 = bx * BN;
    const int lr_ = tid >> 2, lc = (tid & 3) << 2;

    float accR[4][4], accI[4][4];
#pragma unroll
    for (int i = 0; i < 4; i++)
#pragma unroll
        for (int j = 0; j < 4; j++) { accR[i][j] = 0.f; accI[i][j] = 0.f; }

    for (int k0 = 0; k0 < D_; k0 += BK) {
        float4 ar4 = *(const float4*)(Zin + (size_t)(m0+lr_)*TD_ + k0 + lc);
        float4 ai4 = *(const float4*)(Zin + (size_t)(m0+lr_)*TD_ + D_ + k0 + lc);
        float4 wr4 = *(const float4*)(Wr  + (size_t)(n0+lr_)*D_ + k0 + lc);
        float4 wi4 = *(const float4*)(Wi  + (size_t)(n0+lr_)*D_ + k0 + lc);
        Ar[lr_][lc+0]=ar4.x; Ar[lr_][lc+1]=ar4.y; Ar[lr_][lc+2]=ar4.z; Ar[lr_][lc+3]=ar4.w;
        Ai[lr_][lc+0]=ai4.x; Ai[lr_][lc+1]=ai4.y; Ai[lr_][lc+2]=ai4.z; Ai[lr_][lc+3]=ai4.w;
        Br[lr_][lc+0]=wr4.x; Br[lr_][lc+1]=wr4.y; Br[lr_][lc+2]=wr4.z; Br[lr_][lc+3]=wr4.w;
        Bi[lr_][lc+0]=wi4.x; Bi[lr_][lc+1]=wi4.y; Bi[lr_][lc+2]=wi4.z; Bi[lr_][lc+3]=wi4.w;
        __syncthreads();
#pragma unroll
        for (int k = 0; k < BK; k++) {
            float ar[4], ai[4], br[4], bi[4];
#pragma unroll
            for (int i = 0; i < 4; i++) { ar[i] = Ar[ty*4+i][k]; ai[i] = Ai[ty*4+i][k]; }
#pragma unroll
            for (int j = 0; j < 4; j++) { br[j] = Br[tx*4+j][k]; bi[j] = Bi[tx*4+j][k]; }
#pragma unroll
            for (int i = 0; i < 4; i++)
#pragma unroll
                for (int j = 0; j < 4; j++) {
                    accR[i][j] += ar[i]*br[j] - ai[i]*bi[j];
                    accI[i][j] += ai[i]*br[j] + ar[i]*bi[j];
                }
        }
        __syncthreads();
    }
#pragma unroll
    for (int i = 0; i < 4; i++) {
        int m = m0 + ty*4 + i;
#pragma unroll
        for (int j = 0; j < 4; j++) {
            int n = n0 + tx*4 + j;
            float lr = accR[i][j], li = accI[i][j];
            float mm = sqrtf(lr*lr + li*li + EPS_);
            lr = lr / (1.f + mm);
            li = li / (1.f + mm);
            Zout[(size_t)m*TD_ + n]       = tanhf(lr);
            Zout[(size_t)m*TD_ + D_ + n]  = tanhf(li);
        }
    }
}

// ---------------------------------------------------------------------------
// Stage A: cell(sym) | Ksym | Vsym | SymCon | embed | rownorms      368 blocks
// ---------------------------------------------------------------------------
__global__ __launch_bounds__(256)
void stageA_kernel(const float* __restrict__ mag, const float* __restrict__ phase,
                   const float* __restrict__ sym, const float* __restrict__ con,
                   const float* __restrict__ Wr,  const float* __restrict__ Wi,
                   const float* __restrict__ kw,  const float* __restrict__ kb,
                   const float* __restrict__ vw,  const float* __restrict__ vb)
{
    __shared__ float sm[SM_FLOATS];
    const int b = blockIdx.x, tid = threadIdx.x;

    if (b < 64) {                       // cellTab = cell(sym), 512x512
        dev_cell_tile(sym, Wr, Wi, g_cellTab, b & 7, b >> 3, sm);
    } else if (b < 128) {               // Ksym = sym@kw^T+kb  [512,512] K=1024
        int t = b - 64;
        dev_gemm_tile(sym, kw, kb, g_Ksym, D_, TD_, 0, TD_, t & 7, t >> 3, sm);
    } else if (b < 256) {               // Vsym = sym@vw^T+vb  [512,1024] K=1024
        int t = b - 128;
        dev_gemm_tile(sym, vw, vb, g_Vsym, TD_, TD_, 0, TD_, t & 15, t >> 4, sm);
    } else if (b < 264) {               // SymCon = sym@con^T  [512,64] K=1024
        int t = b - 256;
        dev_gemm_tile(sym, con, nullptr, g_SymCon, NCON_, TD_, 0, TD_, 0, t, sm);
    } else if (b < 296) {               // embed: 8 vocab rows per block
        int base = (b - 264) * 8;
#pragma unroll
        for (int vv = 0; vv < 8; vv++) {
            int v = base + vv;
            for (int i = tid; i < D_; i += 256) {
                float r = mag[v*D_ + i];
                float t = phase[v*D_ + i];
                g_embed[v*TD_ + i]      = r * cosf(t);
                g_embed[v*TD_ + D_ + i] = r * sinf(t);
            }
        }
    } else {                            // rownorms: 8 rows/block (warp per row)
        int local = b - 296;            // 0..71
        int wid = tid >> 5, lane = tid & 31;
        int row = local * 8 + wid;      // 0..575
        const float* src = (row < NSYM_) ? (sym + (size_t)row*TD_)
                                         : (con + (size_t)(row - NSYM_)*TD_);
        float s = 0.f;
        for (int i = lane; i < TD_; i += 32) { float v = src[i]; s += v*v; }
#pragma unroll
        for (int o = 16; o > 0; o >>= 1) s += __shfl_down_sync(0xffffffffu, s, o);
        if (lane == 0) {
            if (row < NSYM_) g_sym2[row] = s; else g_con2[row - NSYM_] = s;
        }
    }
}

// ---------------------------------------------------------------------------
// Stage B: z0=cell(embed) | C2=cell(cellTab) | Qtab | CS | VS | conDist  290
// ---------------------------------------------------------------------------
__global__ __launch_bounds__(256)
void stageB_kernel(const float* __restrict__ Wr, const float* __restrict__ Wi,
                   const float* __restrict__ qw, const float* __restrict__ qb,
                   const float* __restrict__ sym)
{
    __shared__ float sm[SM_FLOATS];
    const int b = blockIdx.x, tid = threadIdx.x;

    if (b < 32) {                       // z0 = cell(embed), M=256
        dev_cell_tile(g_embed, Wr, Wi, g_z0, b & 7, b >> 3, sm);
    } else if (b < 96) {                // C2 = cell(cellTab)
        int t = b - 32;
        dev_cell_tile(g_cellTab, Wr, Wi, g_C2, t & 7, t >> 3, sm);
    } else if (b < 160) {               // Qtab = cellTab@qw^T+qb
        int t = b - 96;
        dev_gemm_tile(g_cellTab, qw, qb, g_Qtab, D_, TD_, 0, TD_, t & 7, t >> 3, sm);
    } else if (b < 224) {               // CS = cellTab@sym^T
        int t = b - 160;
        dev_gemm_tile(g_cellTab, sym, nullptr, g_CS, NSYM_, TD_, 0, TD_, t & 7, t >> 3, sm);
    } else if (b < 288) {               // VS = Vsym@sym^T
        int t = b - 224;
        dev_gemm_tile(g_Vsym, sym, nullptr, g_VS, NSYM_, TD_, 0, TD_, t & 7, t >> 3, sm);
    } else {                            // conDist: 2 blocks x 256
        int k = (b - 288) * 256 + tid;
        float best = 1e30f;
        float s2 = g_sym2[k];
        for (int j = 0; j < NCON_; j++) {
            float d = s2 + g_con2[j] - 2.f * g_SymCon[k*NCON_ + j];
            if (d < best) best = d;
        }
        g_conDist[k] = best;
    }
}

// ---------------------------------------------------------------------------
// Stage C: C3=cell(C2) | QK | Z0S                                      160
// ---------------------------------------------------------------------------
__global__ __launch_bounds__(256)
void stageC_kernel(const float* __restrict__ Wr, const float* __restrict__ Wi,
                   const float* __restrict__ sym)
{
    __shared__ float sm[SM_FLOATS];
    const int b = blockIdx.x;

    if (b < 64) {                       // C3 = cell(C2)
        dev_cell_tile(g_C2, Wr, Wi, g_C3, b & 7, b >> 3, sm);
    } else if (b < 128) {               // QK = Qtab@Ksym^T  K=512
        int t = b - 64;
        dev_gemm_tile(g_Qtab, g_Ksym, nullptr, g_QK, NSYM_, D_, 0, D_, t & 7, t >> 3, sm);
    } else {                            // Z0S = z0@sym^T  [256,512] K=1024
        int t = b - 128;
        dev_gemm_tile(g_z0, sym, nullptr, g_Z0S, NSYM_, TD_, 0, TD_, t & 7, t >> 3, sm);
    }
}

// ---------------------------------------------------------------------------
// Trajectory device function (one block, vocab v)
// ---------------------------------------------------------------------------
__device__ void dev_trajectory(int v, float* sm)
{
    float* red   = sm;            // 256
    float* sdist = sm + 256;      // 256
    int*   sidx  = (int*)(sm + 512);   // 256
    int*   memIdx= (int*)(sm + 768);   // 6
    float* wsh   = sm + 776;           // 6
    float* shconf= sm + 784;           // 1
    const int tid = threadIdx.x;

    // ---- iteration 0 ----
    float part = 0.f;
    for (int i = tid; i < TD_; i += 256) { float z = g_z0[(size_t)v*TD_ + i]; part += z*z; }
    red[tid] = part; __syncthreads();
    for (int st = 128; st > 0; st >>= 1) { if (tid < st) red[tid] += red[tid+st]; __syncthreads(); }
    float z2 = red[0];
    __syncthreads();

    float bd = 1e30f; int bi = 0;
    for (int kp = tid; kp < NSYM_; kp += 256) {
        float d = z2 + g_sym2[kp] - 2.f*g_Z0S[(size_t)v*NSYM_ + kp];
        if (d < bd) { bd = d; bi = kp; }
    }
    sdist[tid] = bd; sidx[tid] = bi; __syncthreads();
    for (int st = 128; st > 0; st >>= 1) {
        if (tid < st) {
            float d2 = sdist[tid+st]; int i2 = sidx[tid+st];
            if (d2 < sdist[tid] || (d2 == sdist[tid] && i2 < sidx[tid])) { sdist[tid] = d2; sidx[tid] = i2; }
        }
        __syncthreads();
    }
    int si = sidx[0]; float sd = sdist[0];
    if (tid == 0) { memIdx[0] = si; shconf[0] = 1.f/(1.f + sd); }
    float symL = sd;
    float conL = g_conDist[si];
    __syncthreads();

    // ---- iterations 1..5 ----
    for (int d = 1; d < DEPTH_; d++) {
        int k = memIdx[d-1];
        if (tid == 0) {
            float sc[DEPTH_]; float mx = -1e30f;
            float cf = shconf[0];
            for (int j = 0; j < d; j++) {
                float s = g_QK[(size_t)k*NSYM_ + memIdx[j]] * SCALE_ * cf;
                sc[j] = s; if (s > mx) mx = s;
            }
            float se = 0.f;
            for (int j = 0; j < d; j++) { sc[j] = expf(sc[j]-mx); se += sc[j]; }
            for (int j = 0; j < d; j++) wsh[j] = sc[j]/se;
        }
        __syncthreads();

        part = 0.f;
        for (int i = tid; i < TD_; i += 256) {
            float z = g_cellTab[(size_t)k*TD_ + i];
            for (int j = 0; j < d; j++)
                z += 0.1f * wsh[j] * g_Vsym[(size_t)memIdx[j]*TD_ + i];
            part += z*z;
        }
        red[tid] = part; __syncthreads();
        for (int st = 128; st > 0; st >>= 1) { if (tid < st) red[tid] += red[tid+st]; __syncthreads(); }
        z2 = red[0];
        __syncthreads();

        bd = 1e30f; bi = 0;
        for (int kp = tid; kp < NSYM_; kp += 256) {
            float zdot = g_CS[(size_t)k*NSYM_ + kp];
            for (int j = 0; j < d; j++)
                zdot += 0.1f * wsh[j] * g_VS[(size_t)memIdx[j]*NSYM_ + kp];
            float dist = z2 + g_sym2[kp] - 2.f*zdot;
            if (dist < bd) { bd = dist; bi = kp; }
        }
        sdist[tid] = bd; sidx[tid] = bi; __syncthreads();
        for (int st = 128; st > 0; st >>= 1) {
            if (tid < st) {
                float d2 = sdist[tid+st]; int i2 = sidx[tid+st];
                if (d2 < sdist[tid] || (d2 == sdist[tid] && i2 < sidx[tid])) { sdist[tid] = d2; sidx[tid] = i2; }
            }
            __syncthreads();
        }
        si = sidx[0]; sd = sdist[0];
        if (tid == 0) { memIdx[d] = si; shconf[0] = 1.f/(1.f + sd); }
        symL += sd;
        conL += g_conDist[si];
        __syncthreads();
    }

    if (tid == 0) {
        g_fin[v]   = memIdx[DEPTH_-1];
        g_symLv[v] = symL;
        g_conLv[v] = conL;
    }
}

// ---------------------------------------------------------------------------
// Stage DE: trajectory (256) | lookOut split-K x4 (128)                384
// ---------------------------------------------------------------------------
__global__ __launch_bounds__(256)
void stageDE_kernel(const float* __restrict__ dec_w, const float* __restrict__ dec_b)
{
    __shared__ float sm[SM_FLOATS];
    const int b = blockIdx.x;

    if (b < NV_) {
        dev_trajectory(b, sm);
    } else {
        int local = b - NV_;             // 0..127
        int partk = local >> 5;          // 0..3
        int t = local & 31;              // 32 tiles: bx 0..3, by 0..7
        int kBeg = partk * 256, kEnd = kBeg + 256;
        const float* bias = (partk == 0) ? dec_b : nullptr;
        dev_gemm_tile(g_C3, dec_w, bias, g_lookP[partk],
                      NV_, TD_, kBeg, kEnd, t & 3, t >> 2, sm);
    }
}

// ---------------------------------------------------------------------------
// Stage F: scatter (4096 blocks) + histogram losses (1 block)
// ---------------------------------------------------------------------------
__global__ __launch_bounds__(256)
void stageF_kernel(const int* __restrict__ x, float* __restrict__ out, int writeLoss)
{
    const int b = blockIdx.x, tid = threadIdx.x;

    if (b < 4096) {
        int gid = b * 256 + tid;         // 1,048,576 float4 slots
        int p = gid >> 6;                // position 0..16383
        int c = gid & 63;                // float4 chunk within 256-float row
        int v = __ldg(&x[p]);
        int f = g_fin[v];
        const float4* p0 = (const float4*)(g_lookP[0] + (size_t)f*NV_);
        const float4* p1 = (const float4*)(g_lookP[1] + (size_t)f*NV_);
        const float4* p2 = (const float4*)(g_lookP[2] + (size_t)f*NV_);
        const float4* p3 = (const float4*)(g_lookP[3] + (size_t)f*NV_);
        float4 a = p0[c], bb = p1[c], cc = p2[c], dd = p3[c];
        float4 r;
        r.x = a.x + bb.x + cc.x + dd.x;
        r.y = a.y + bb.y + cc.y + dd.y;
        r.z = a.z + bb.z + cc.z + dd.z;
        r.w = a.w + bb.w + cc.w + dd.w;
        ((float4*)out)[gid] = r;
    } else {
        __shared__ int   hist[NV_];
        __shared__ float red[256];
        hist[tid] = 0; __syncthreads();
        for (int i = tid; i < NPOS_; i += 256) atomicAdd(&hist[x[i]], 1);
        __syncthreads();

        float h = (float)hist[tid];
        float s = h * g_symLv[tid];
        float c = h * g_conLv[tid];

        red[tid] = s; __syncthreads();
        for (int st = 128; st > 0; st >>= 1) { if (tid < st) red[tid] += red[tid+st]; __syncthreads(); }
        float st_tot = red[0]; __syncthreads();

        red[tid] = c; __syncthreads();
        for (int st = 128; st > 0; st >>= 1) { if (tid < st) red[tid] += red[tid+st]; __syncthreads(); }
        float ct_tot = red[0];

        if (tid == 0 && writeLoss) {
            float norm = (1.f + CC_) / (float)((size_t)NPOS_ * TD_);
            out[(size_t)NPOS_*NV_]     = st_tot * norm;
            out[(size_t)NPOS_*NV_ + 1] = ct_tot * norm;
        }
    }
}

// ---------------------------------------------------------------------------
// Host launcher
// ---------------------------------------------------------------------------
extern "C" void kernel_launch(void* const* d_in, const int* in_sizes, int n_in,
                              void* d_out, int out_size)
{
    const int*   x     = (const int*)d_in[0];
    const float* mag   = (const float*)d_in[1];
    const float* phase = (const float*)d_in[2];
    const float* Wr    = (const float*)d_in[3];
    const float* Wi    = (const float*)d_in[4];
    const float* qw    = (const float*)d_in[5];
    const float* qb    = (const float*)d_in[6];
    const float* kw    = (const float*)d_in[7];
    const float* kb    = (const float*)d_in[8];
    const float* vw    = (const float*)d_in[9];
    const float* vb    = (const float*)d_in[10];
    const float* dec_w = (const float*)d_in[11];
    const float* dec_b = (const float*)d_in[12];
    const float* sym   = (const float*)d_in[13];
    const float* con   = (const float*)d_in[14];
    float* out = (float*)d_out;

    int writeLoss = (out_size >= NPOS_*NV_ + 2) ? 1 : 0;

    stageA_kernel<<<368, 256>>>(mag, phase, sym, con, Wr, Wi, kw, kb, vw, vb);
    stageB_kernel<<<290, 256>>>(Wr, Wi, qw, qb, sym);
    stageC_kernel<<<160, 256>>>(Wr, Wi, sym);
    stageDE_kernel<<<384, 256>>>(dec_w, dec_b);
    stageF_kernel<<<4097, 256>>>(x, out, writeLoss);
}